// round 1
// baseline (speedup 1.0000x reference)
#include <cuda_runtime.h>
#include <cuda_bf16.h>
#include <math.h>

#define NMAX 50000
#define DIM 128
#define KNBR 16
#define MT 32   // GEMM row tile

// Scratch (static device globals — no allocation allowed)
__device__ float g_H1[(size_t)NMAX * DIM];
__device__ float g_H2[(size_t)NMAX * DIM];
__device__ float g_C[(size_t)NMAX * 2 * DIM];

// ---------------------------------------------------------------------------
// Mean neighbor aggregation: out[n] = mean_k in[nbr[n][k]]
// One warp per node, lane owns 4 contiguous floats (float4).
// ---------------------------------------------------------------------------
__global__ void agg_kernel(const float* __restrict__ in,
                           const int* __restrict__ nbr,
                           float* __restrict__ out, int N) {
    int warp = (blockIdx.x * blockDim.x + threadIdx.x) >> 5;
    int lane = threadIdx.x & 31;
    if (warp >= N) return;
    const int* nb = nbr + (size_t)warp * KNBR;
    const float4* in4 = (const float4*)in;
    float4 acc = make_float4(0.f, 0.f, 0.f, 0.f);
#pragma unroll
    for (int k = 0; k < KNBR; k++) {
        int idx = __ldg(nb + k);
        float4 v = __ldg(in4 + (size_t)idx * 32 + lane);
        acc.x += v.x; acc.y += v.y; acc.z += v.z; acc.w += v.w;
    }
    const float s = 1.0f / (float)KNBR;
    float4 r = make_float4(acc.x * s, acc.y * s, acc.z * s, acc.w * s);
    ((float4*)out)[(size_t)warp * 32 + lane] = r;
}

// ---------------------------------------------------------------------------
// C[N,256] = H[N,128] @ Wcat[128,256]
// Wcat[k][c] = (c < 128) ? W1[k][c] : W1[k+128][c-128]
// Persistent blocks: Wcat (128KB) loaded once to smem per block.
// 256 threads: thread owns 8 rows x 4 cols (float4 accumulators).
// ---------------------------------------------------------------------------
extern __shared__ float s_dyn[];

__global__ __launch_bounds__(256, 1) void gemm_kernel(const float* __restrict__ H,
                                                      const float* __restrict__ W1,
                                                      float* __restrict__ C, int N) {
    float* Ws = s_dyn;                 // [128][256]
    float* Hs = s_dyn + 128 * 256;     // [MT][128]
    int t = threadIdx.x;

    // Load concatenated weight into smem (coalesced over W1 rows)
    for (int idx = t; idx < 128 * 256; idx += 256) {
        int k = idx >> 8;
        int c = idx & 255;
        Ws[idx] = (c < 128) ? W1[k * 128 + c] : W1[(k + 128) * 128 + (c - 128)];
    }

    int cg = t & 63;   // column group: cols [4*cg, 4*cg+4)
    int rg = t >> 6;   // row group: rows [8*rg, 8*rg+8) within tile
    int numTiles = (N + MT - 1) / MT;

    for (int tile = blockIdx.x; tile < numTiles; tile += gridDim.x) {
        int row0 = tile * MT;
        __syncthreads();  // previous compute done (and Ws ready on first iter)
        int vrows = min(MT, N - row0);
        const float4* H4 = (const float4*)(H + (size_t)row0 * 128);
        float4* Hs4 = (float4*)Hs;
        for (int i = t; i < vrows * 32; i += 256) Hs4[i] = H4[i];
        __syncthreads();

        float4 acc[8];
#pragma unroll
        for (int r = 0; r < 8; r++) acc[r] = make_float4(0.f, 0.f, 0.f, 0.f);

        const float4* Ws4 = (const float4*)Ws;
#pragma unroll 8
        for (int k = 0; k < 128; k++) {
            float4 w = Ws4[k * 64 + cg];
#pragma unroll
            for (int r = 0; r < 8; r++) {
                float h = Hs[(rg * 8 + r) * 128 + k];
                acc[r].x += h * w.x;
                acc[r].y += h * w.y;
                acc[r].z += h * w.z;
                acc[r].w += h * w.w;
            }
        }
#pragma unroll
        for (int r = 0; r < 8; r++) {
            int row = row0 + rg * 8 + r;
            if (row < N) ((float4*)C)[(size_t)row * 64 + cg] = acc[r];
        }
    }
}

// ---------------------------------------------------------------------------
// Per-pair: h = relu(C[src][0:128] + C[dst][128:256] + b1); logits = h@W2+b2;
// loss_i = logsumexp(softmax(logits)) - softmax(logits)[label]; atomic mean.
// One warp per pair (grid-strided), lane owns 4 features.
// ---------------------------------------------------------------------------
__global__ void pair_kernel(const int* __restrict__ pairs,
                            const int* __restrict__ labels,
                            const float* __restrict__ C,
                            const float* __restrict__ b1,
                            const float* __restrict__ W2,
                            const float* __restrict__ b2,
                            float* __restrict__ out, int B) {
    int lane = threadIdx.x & 31;
    int wib = threadIdx.x >> 5;
    int warpsPerBlock = blockDim.x >> 5;
    int gwarp = blockIdx.x * warpsPerBlock + wib;
    int nwarps = gridDim.x * warpsPerBlock;

    float4 bias = __ldg((const float4*)b1 + lane);
    float w20[4], w21[4];
#pragma unroll
    for (int q = 0; q < 4; q++) {
        w20[q] = __ldg(W2 + (lane * 4 + q) * 2 + 0);
        w21[q] = __ldg(W2 + (lane * 4 + q) * 2 + 1);
    }
    float b2_0 = __ldg(b2 + 0), b2_1 = __ldg(b2 + 1);

    const float4* C4 = (const float4*)C;
    float lsum = 0.f;

    for (int p = gwarp; p < B; p += nwarps) {
        int src = __ldg(pairs + 2 * p);
        int dst = __ldg(pairs + 2 * p + 1);
        float4 a  = __ldg(C4 + (size_t)src * 64 + lane);
        float4 bb = __ldg(C4 + (size_t)dst * 64 + 32 + lane);
        float h0 = fmaxf(a.x + bb.x + bias.x, 0.f);
        float h1 = fmaxf(a.y + bb.y + bias.y, 0.f);
        float h2 = fmaxf(a.z + bb.z + bias.z, 0.f);
        float h3 = fmaxf(a.w + bb.w + bias.w, 0.f);
        float l0 = h0 * w20[0] + h1 * w20[1] + h2 * w20[2] + h3 * w20[3];
        float l1 = h0 * w21[0] + h1 * w21[1] + h2 * w21[2] + h3 * w21[3];
#pragma unroll
        for (int off = 16; off > 0; off >>= 1) {
            l0 += __shfl_down_sync(0xFFFFFFFFu, l0, off);
            l1 += __shfl_down_sync(0xFFFFFFFFu, l1, off);
        }
        if (lane == 0) {
            l0 += b2_0; l1 += b2_1;
            // probs = softmax(logits)
            float m = fmaxf(l0, l1);
            float e0 = expf(l0 - m), e1 = expf(l1 - m);
            float inv = 1.f / (e0 + e1);
            float p0 = e0 * inv, p1 = e1 * inv;
            // logp = probs - logsumexp(probs)
            float mm = fmaxf(p0, p1);
            float lse = mm + logf(expf(p0 - mm) + expf(p1 - mm));
            int lab = __ldg(labels + p);
            float pl = lab ? p1 : p0;
            lsum += (lse - pl);
        }
    }

    __shared__ float ssum[32];
    if (lane == 0) ssum[wib] = lsum;
    __syncthreads();
    if (threadIdx.x == 0) {
        float s = 0.f;
        for (int w = 0; w < warpsPerBlock; w++) s += ssum[w];
        atomicAdd(out, s / (float)B);
    }
}

__global__ void zero_kernel(float* out, int n) {
    int i = blockIdx.x * blockDim.x + threadIdx.x;
    if (i < n) out[i] = 0.f;
}

// ---------------------------------------------------------------------------
extern "C" void kernel_launch(void* const* d_in, const int* in_sizes, int n_in,
                              void* d_out, int out_size) {
    const int*   pairs     = (const int*)d_in[0];
    const int*   labels    = (const int*)d_in[1];
    const int*   neighbors = (const int*)d_in[2];
    const float* embedding = (const float*)d_in[3];
    const float* W1        = (const float*)d_in[4];
    const float* b1        = (const float*)d_in[5];
    const float* W2        = (const float*)d_in[6];
    const float* b2        = (const float*)d_in[7];

    int B = in_sizes[0] / 2;
    int N = in_sizes[2] / KNBR;

    float *H1, *H2, *C;
    cudaGetSymbolAddress((void**)&H1, g_H1);
    cudaGetSymbolAddress((void**)&H2, g_H2);
    cudaGetSymbolAddress((void**)&C,  g_C);

    float* out = (float*)d_out;
    zero_kernel<<<(out_size + 255) / 256, 256>>>(out, out_size);

    // 2 aggregation layers
    int aggBlocks = (N + 7) / 8;  // 8 warps/block, warp per node
    agg_kernel<<<aggBlocks, 256>>>(embedding, neighbors, H1, N);
    agg_kernel<<<aggBlocks, 256>>>(H1, neighbors, H2, N);

    // Projection GEMM: C = H2 @ Wcat  (persistent blocks, full W in smem)
    size_t smem = (size_t)(128 * 256 + MT * 128) * sizeof(float);
    static int attr_set = 0;
    cudaFuncSetAttribute(gemm_kernel, cudaFuncAttributeMaxDynamicSharedMemorySize, (int)smem);
    (void)attr_set;
    gemm_kernel<<<148, 256, smem>>>(H2, W1, C, N);

    // Pair loss
    pair_kernel<<<1184, 256>>>(pairs, labels, C, b1, W2, b2, out, B);
}

// round 2
// speedup vs baseline: 1.4297x; 1.4297x over previous
#include <cuda_runtime.h>
#include <cuda_bf16.h>
#include <math.h>

#define NMAX 50000
#define DIM 128
#define KNBR 16
#define GMT 64            // GEMM row tile
#define WS_STRIDE 264     // Wcat smem row stride (conflict-free B frags)
#define HS_STRIDE 132     // H smem row stride (conflict-free A frags)

// Scratch (static device globals — no allocation allowed)
__device__ float g_H1[(size_t)NMAX * DIM];
__device__ float g_H2[(size_t)NMAX * DIM];
__device__ float g_C[(size_t)NMAX * 2 * DIM];

// ---------------------------------------------------------------------------
// Mean neighbor aggregation: out[n] = mean_k in[nbr[n][k]]
// One warp per node, lane owns 4 contiguous floats (float4).
// ---------------------------------------------------------------------------
__global__ void agg_kernel(const float* __restrict__ in,
                           const int* __restrict__ nbr,
                           float* __restrict__ out, int N) {
    int warp = (blockIdx.x * blockDim.x + threadIdx.x) >> 5;
    int lane = threadIdx.x & 31;
    if (warp >= N) return;
    const int* nb = nbr + (size_t)warp * KNBR;
    const float4* in4 = (const float4*)in;
    float4 acc = make_float4(0.f, 0.f, 0.f, 0.f);
#pragma unroll
    for (int k = 0; k < KNBR; k++) {
        int idx = __ldg(nb + k);
        float4 v = __ldg(in4 + (size_t)idx * 32 + lane);
        acc.x += v.x; acc.y += v.y; acc.z += v.z; acc.w += v.w;
    }
    const float s = 1.0f / (float)KNBR;
    float4 r = make_float4(acc.x * s, acc.y * s, acc.z * s, acc.w * s);
    ((float4*)out)[(size_t)warp * 32 + lane] = r;
}

// ---------------------------------------------------------------------------
// tf32 helpers
// ---------------------------------------------------------------------------
__device__ __forceinline__ unsigned f2tf32(float f) {
    unsigned u;
    asm("cvt.rna.tf32.f32 %0, %1;" : "=r"(u) : "f"(f));
    return u;
}

__device__ __forceinline__ void mma_tf32(float* d, const unsigned* a, const unsigned* b) {
    asm("mma.sync.aligned.m16n8k8.row.col.f32.tf32.tf32.f32 "
        "{%0,%1,%2,%3}, {%4,%5,%6,%7}, {%8,%9}, {%0,%1,%2,%3};"
        : "+f"(d[0]), "+f"(d[1]), "+f"(d[2]), "+f"(d[3])
        : "r"(a[0]), "r"(a[1]), "r"(a[2]), "r"(a[3]), "r"(b[0]), "r"(b[1]));
}

// ---------------------------------------------------------------------------
// C[N,256] = H[N,128] @ Wcat[128,256]   (tf32 tensor cores)
// Wcat[k][c] = (c < 128) ? W1[k][c] : W1[k+128][c-128]
// Persistent 148 CTAs x 256 threads. Full Wcat in smem (tf32, stride 264).
// CTA tile: 64 rows x 256 cols. Warp w owns cols [32w, 32w+32).
// Warp: m-frags 4 (16 rows each), n-frags 4 (8 cols each) -> 16 acc frags.
// ---------------------------------------------------------------------------
extern __shared__ unsigned s_dyn_u[];

__global__ __launch_bounds__(256, 1) void gemm_kernel(const float* __restrict__ H,
                                                      const float* __restrict__ W1,
                                                      float* __restrict__ C, int N) {
    unsigned* Ws = s_dyn_u;                          // [128][WS_STRIDE]
    unsigned* Hs = s_dyn_u + 128 * WS_STRIDE;        // [GMT][HS_STRIDE]
    int t = threadIdx.x;
    int lane = t & 31;
    int warp = t >> 5;
    int n0 = warp * 32;
    int ar = lane >> 2;   // fragment row group
    int ac = lane & 3;    // fragment col group

    // Load concatenated weight into smem as tf32
    for (int idx = t; idx < 128 * 256; idx += 256) {
        int k = idx >> 8;
        int c = idx & 255;
        float v = (c < 128) ? W1[k * 128 + c] : W1[(k + 128) * 128 + (c - 128)];
        Ws[k * WS_STRIDE + c] = f2tf32(v);
    }

    int numTiles = (N + GMT - 1) / GMT;

    for (int tile = blockIdx.x; tile < numTiles; tile += gridDim.x) {
        int row0 = tile * GMT;
        __syncthreads();  // protect Hs reuse; first iter also orders Ws fill

        // Load H tile -> smem tf32 (stride HS_STRIDE), zero-pad tail rows
        for (int i = t; i < GMT * 32; i += 256) {
            int row = i >> 5;
            int q = i & 31;
            float4 v = make_float4(0.f, 0.f, 0.f, 0.f);
            if (row0 + row < N)
                v = __ldg((const float4*)H + (size_t)(row0 + row) * 32 + q);
            uint4 u;
            u.x = f2tf32(v.x); u.y = f2tf32(v.y);
            u.z = f2tf32(v.z); u.w = f2tf32(v.w);
            *(uint4*)(Hs + row * HS_STRIDE + q * 4) = u;
        }
        __syncthreads();

        float acc[4][4][4];
#pragma unroll
        for (int mf = 0; mf < 4; mf++)
#pragma unroll
            for (int nf = 0; nf < 4; nf++)
#pragma unroll
                for (int e = 0; e < 4; e++) acc[mf][nf][e] = 0.f;

#pragma unroll
        for (int kc = 0; kc < 128; kc += 8) {
            unsigned a[4][4];
#pragma unroll
            for (int mf = 0; mf < 4; mf++) {
                int base = (mf * 16 + ar) * HS_STRIDE + kc + ac;
                a[mf][0] = Hs[base];
                a[mf][1] = Hs[base + 4];
                a[mf][2] = Hs[base + 8 * HS_STRIDE];
                a[mf][3] = Hs[base + 8 * HS_STRIDE + 4];
            }
            unsigned b[4][2];
#pragma unroll
            for (int nf = 0; nf < 4; nf++) {
                int base = (kc + ac) * WS_STRIDE + n0 + nf * 8 + ar;
                b[nf][0] = Ws[base];
                b[nf][1] = Ws[base + 4 * WS_STRIDE];
            }
#pragma unroll
            for (int mf = 0; mf < 4; mf++)
#pragma unroll
                for (int nf = 0; nf < 4; nf++)
                    mma_tf32(acc[mf][nf], a[mf], b[nf]);
        }

        // Epilogue: c0,c1 at (row, 2*ac), c2,c3 at (row+8, 2*ac)
#pragma unroll
        for (int mf = 0; mf < 4; mf++) {
            int r_lo = row0 + mf * 16 + ar;
            int r_hi = r_lo + 8;
#pragma unroll
            for (int nf = 0; nf < 4; nf++) {
                int col = n0 + nf * 8 + ac * 2;
                if (r_lo < N)
                    *(float2*)(C + (size_t)r_lo * 256 + col) =
                        make_float2(acc[mf][nf][0], acc[mf][nf][1]);
                if (r_hi < N)
                    *(float2*)(C + (size_t)r_hi * 256 + col) =
                        make_float2(acc[mf][nf][2], acc[mf][nf][3]);
            }
        }
    }
}

// ---------------------------------------------------------------------------
// Per-pair: h = relu(C[src][0:128] + C[dst][128:256] + b1); logits = h@W2+b2;
// loss_i = logsumexp(softmax(logits)) - softmax(logits)[label]; atomic mean.
// One warp per pair (grid-strided), lane owns 4 features.
// ---------------------------------------------------------------------------
__global__ void pair_kernel(const int* __restrict__ pairs,
                            const int* __restrict__ labels,
                            const float* __restrict__ C,
                            const float* __restrict__ b1,
                            const float* __restrict__ W2,
                            const float* __restrict__ b2,
                            float* __restrict__ out, int B) {
    int lane = threadIdx.x & 31;
    int wib = threadIdx.x >> 5;
    int warpsPerBlock = blockDim.x >> 5;
    int gwarp = blockIdx.x * warpsPerBlock + wib;
    int nwarps = gridDim.x * warpsPerBlock;

    float4 bias = __ldg((const float4*)b1 + lane);
    float w20[4], w21[4];
#pragma unroll
    for (int q = 0; q < 4; q++) {
        w20[q] = __ldg(W2 + (lane * 4 + q) * 2 + 0);
        w21[q] = __ldg(W2 + (lane * 4 + q) * 2 + 1);
    }
    float b2_0 = __ldg(b2 + 0), b2_1 = __ldg(b2 + 1);

    const float4* C4 = (const float4*)C;
    float lsum = 0.f;

    for (int p = gwarp; p < B; p += nwarps) {
        int src = __ldg(pairs + 2 * p);
        int dst = __ldg(pairs + 2 * p + 1);
        float4 a  = __ldg(C4 + (size_t)src * 64 + lane);
        float4 bb = __ldg(C4 + (size_t)dst * 64 + 32 + lane);
        float h0 = fmaxf(a.x + bb.x + bias.x, 0.f);
        float h1 = fmaxf(a.y + bb.y + bias.y, 0.f);
        float h2 = fmaxf(a.z + bb.z + bias.z, 0.f);
        float h3 = fmaxf(a.w + bb.w + bias.w, 0.f);
        float l0 = h0 * w20[0] + h1 * w20[1] + h2 * w20[2] + h3 * w20[3];
        float l1 = h0 * w21[0] + h1 * w21[1] + h2 * w21[2] + h3 * w21[3];
#pragma unroll
        for (int off = 16; off > 0; off >>= 1) {
            l0 += __shfl_down_sync(0xFFFFFFFFu, l0, off);
            l1 += __shfl_down_sync(0xFFFFFFFFu, l1, off);
        }
        if (lane == 0) {
            l0 += b2_0; l1 += b2_1;
            // probs = softmax(logits)
            float m = fmaxf(l0, l1);
            float e0 = expf(l0 - m), e1 = expf(l1 - m);
            float inv = 1.f / (e0 + e1);
            float p0 = e0 * inv, p1 = e1 * inv;
            // logp = probs - logsumexp(probs)
            float mm = fmaxf(p0, p1);
            float lse = mm + logf(expf(p0 - mm) + expf(p1 - mm));
            int lab = __ldg(labels + p);
            float pl = lab ? p1 : p0;
            lsum += (lse - pl);
        }
    }

    __shared__ float ssum[32];
    if (lane == 0) ssum[wib] = lsum;
    __syncthreads();
    if (threadIdx.x == 0) {
        float s = 0.f;
        for (int w = 0; w < warpsPerBlock; w++) s += ssum[w];
        atomicAdd(out, s / (float)B);
    }
}

__global__ void zero_kernel(float* out, int n) {
    int i = blockIdx.x * blockDim.x + threadIdx.x;
    if (i < n) out[i] = 0.f;
}

// ---------------------------------------------------------------------------
extern "C" void kernel_launch(void* const* d_in, const int* in_sizes, int n_in,
                              void* d_out, int out_size) {
    const int*   pairs     = (const int*)d_in[0];
    const int*   labels    = (const int*)d_in[1];
    const int*   neighbors = (const int*)d_in[2];
    const float* embedding = (const float*)d_in[3];
    const float* W1        = (const float*)d_in[4];
    const float* b1        = (const float*)d_in[5];
    const float* W2        = (const float*)d_in[6];
    const float* b2        = (const float*)d_in[7];

    int B = in_sizes[0] / 2;
    int N = in_sizes[2] / KNBR;

    float *H1, *H2, *C;
    cudaGetSymbolAddress((void**)&H1, g_H1);
    cudaGetSymbolAddress((void**)&H2, g_H2);
    cudaGetSymbolAddress((void**)&C,  g_C);

    float* out = (float*)d_out;
    zero_kernel<<<(out_size + 255) / 256, 256>>>(out, out_size);

    // 2 aggregation layers
    int aggBlocks = (N + 7) / 8;  // 8 warps/block, warp per node
    agg_kernel<<<aggBlocks, 256>>>(embedding, neighbors, H1, N);
    agg_kernel<<<aggBlocks, 256>>>(H1, neighbors, H2, N);

    // Projection GEMM: C = H2 @ Wcat  (tf32 mma, persistent, full W in smem)
    size_t smem = (size_t)(128 * WS_STRIDE + GMT * HS_STRIDE) * sizeof(unsigned);
    cudaFuncSetAttribute(gemm_kernel, cudaFuncAttributeMaxDynamicSharedMemorySize, (int)smem);
    gemm_kernel<<<148, 256, smem>>>(H2, W1, C, N);

    // Pair loss
    pair_kernel<<<1184, 256>>>(pairs, labels, C, b1, W2, b2, out, B);
}

// round 3
// speedup vs baseline: 1.6978x; 1.1875x over previous
#include <cuda_runtime.h>
#include <cuda_fp16.h>
#include <cuda_bf16.h>
#include <math.h>

#define NMAX 50000
#define DIM 128
#define KNBR 16
#define HSW 68   // smem row stride in 32-bit words (64 data + 4 pad; 68%32==4)

// Scratch (static device globals — no allocation allowed)
__device__ __half g_E [(size_t)NMAX * DIM];
__device__ __half g_H1[(size_t)NMAX * DIM];
__device__ __half g_H2[(size_t)NMAX * DIM];
__device__ float  g_C [(size_t)NMAX * 2 * DIM];

// ---------------------------------------------------------------------------
// fp32 -> fp16 elementwise convert (vectorized)
// ---------------------------------------------------------------------------
__global__ void f2h_kernel(const float* __restrict__ in, __half* __restrict__ out, int n4) {
    int i = blockIdx.x * blockDim.x + threadIdx.x;
    if (i < n4) {
        float4 v = __ldg((const float4*)in + i);
        __half2 lo = __floats2half2_rn(v.x, v.y);
        __half2 hi = __floats2half2_rn(v.z, v.w);
        uint2 u;
        u.x = *(unsigned*)&lo;
        u.y = *(unsigned*)&hi;
        ((uint2*)out)[i] = u;
    }
}

// ---------------------------------------------------------------------------
// Mean neighbor aggregation in fp16: out[n] = mean_k in[nbr[n][k]]
// One warp per node; lane owns 4 halves (8B). Accumulate in fp32.
// ---------------------------------------------------------------------------
__global__ void agg_kernel(const __half* __restrict__ in,
                           const int* __restrict__ nbr,
                           __half* __restrict__ out, int N) {
    int warp = (blockIdx.x * blockDim.x + threadIdx.x) >> 5;
    int lane = threadIdx.x & 31;
    if (warp >= N) return;
    const int* nb = nbr + (size_t)warp * KNBR;
    const uint2* in8 = (const uint2*)in;   // 32 uint2 per 128-half row
    float2 a0 = make_float2(0.f, 0.f), a1 = make_float2(0.f, 0.f);
#pragma unroll
    for (int k = 0; k < KNBR; k++) {
        int idx = __ldg(nb + k);
        uint2 u = __ldg(in8 + (size_t)idx * 32 + lane);
        float2 f0 = __half22float2(*(__half2*)&u.x);
        float2 f1 = __half22float2(*(__half2*)&u.y);
        a0.x += f0.x; a0.y += f0.y;
        a1.x += f1.x; a1.y += f1.y;
    }
    const float s = 1.0f / (float)KNBR;
    __half2 h0 = __floats2half2_rn(a0.x * s, a0.y * s);
    __half2 h1 = __floats2half2_rn(a1.x * s, a1.y * s);
    uint2 r;
    r.x = *(unsigned*)&h0;
    r.y = *(unsigned*)&h1;
    ((uint2*)out)[(size_t)warp * 32 + lane] = r;
}

// ---------------------------------------------------------------------------
// fp16 MMA helper
// ---------------------------------------------------------------------------
__device__ __forceinline__ void mma_f16(float* d, const unsigned* a, const unsigned* b) {
    asm("mma.sync.aligned.m16n8k16.row.col.f32.f16.f16.f32 "
        "{%0,%1,%2,%3}, {%4,%5,%6,%7}, {%8,%9}, {%0,%1,%2,%3};"
        : "+f"(d[0]), "+f"(d[1]), "+f"(d[2]), "+f"(d[3])
        : "r"(a[0]), "r"(a[1]), "r"(a[2]), "r"(a[3]), "r"(b[0]), "r"(b[1]));
}

// ---------------------------------------------------------------------------
// C[N,256] = H[N,128] @ Wcat[128,256]   (fp16 inputs, fp32 accumulate)
// Wcat[k][c] = (c<128) ? W1[k][c] : W1[k+128][c-128]
// Ws stored TRANSPOSED in smem: Ws[n][k] halves, row stride HSW words.
// Hs: [64][128] halves, row stride HSW words. Both conflict-free for frags.
// 296 persistent CTAs x 256 threads, 2 CTAs/SM. Warp w owns cols [32w,32w+32).
// ---------------------------------------------------------------------------
extern __shared__ unsigned s_dyn_u[];

__global__ __launch_bounds__(256, 2) void gemm_kernel(const __half* __restrict__ H,
                                                      const float* __restrict__ W1,
                                                      float* __restrict__ C, int N) {
    unsigned* Ws = s_dyn_u;             // [256][HSW] words (halves [256][2*HSW])
    unsigned* Hs = s_dyn_u + 256 * HSW; // [64][HSW] words
    int t = threadIdx.x;
    int lane = t & 31;
    int warp = t >> 5;
    int g  = lane >> 2;    // fragment group (row/col group)
    int tg = lane & 3;     // thread-in-group
    int n0 = warp * 32;

    // Fill Ws (coalesced over W1 columns; one-time per CTA)
    __half* Wsh = (__half*)Ws;
    for (int idx = t; idx < 256 * 128; idx += 256) {
        int k = idx >> 8;
        int n = idx & 255;
        float v = (n < 128) ? W1[k * 128 + n] : W1[(k + 128) * 128 + (n - 128)];
        Wsh[n * (2 * HSW) + k] = __float2half_rn(v);
    }

    int numTiles = (N + 63) >> 6;

    for (int tile = blockIdx.x; tile < numTiles; tile += gridDim.x) {
        int row0 = tile * 64;
        __syncthreads();  // protect Hs reuse (first iter also orders Ws fill)

        // Load H tile (64 rows x 16 uint4) into Hs
        for (int i = t; i < 64 * 16; i += 256) {
            int row = i >> 4;
            int q = i & 15;
            uint4 v = make_uint4(0u, 0u, 0u, 0u);
            if (row0 + row < N)
                v = __ldg((const uint4*)H + (size_t)(row0 + row) * 16 + q);
            *(uint4*)(Hs + row * HSW + q * 4) = v;
        }
        __syncthreads();

        float acc[4][4][4];
#pragma unroll
        for (int mf = 0; mf < 4; mf++)
#pragma unroll
            for (int nf = 0; nf < 4; nf++)
#pragma unroll
                for (int e = 0; e < 4; e++) acc[mf][nf][e] = 0.f;

#pragma unroll
        for (int kk = 0; kk < 8; kk++) {   // 8 chunks of K=16
            unsigned a[4][4];
#pragma unroll
            for (int mf = 0; mf < 4; mf++) {
                int base = (mf * 16 + g) * HSW + kk * 8 + tg;
                a[mf][0] = Hs[base];                 // (g,     2tg..)
                a[mf][1] = Hs[base + 8 * HSW];       // (g+8,   2tg..)
                a[mf][2] = Hs[base + 4];             // (g,     2tg+8..)
                a[mf][3] = Hs[base + 8 * HSW + 4];   // (g+8,   2tg+8..)
            }
            unsigned b[4][2];
#pragma unroll
            for (int nf = 0; nf < 4; nf++) {
                int base = (n0 + nf * 8 + g) * HSW + kk * 8 + tg;
                b[nf][0] = Ws[base];       // k = 2tg..,   col n
                b[nf][1] = Ws[base + 4];   // k = 2tg+8..
            }
#pragma unroll
            for (int mf = 0; mf < 4; mf++)
#pragma unroll
                for (int nf = 0; nf < 4; nf++)
                    mma_f16(acc[mf][nf], a[mf], b[nf]);
        }

        // Epilogue: c0,c1 at (g, 2tg), c2,c3 at (g+8, 2tg)
#pragma unroll
        for (int mf = 0; mf < 4; mf++) {
            int r_lo = row0 + mf * 16 + g;
            int r_hi = r_lo + 8;
#pragma unroll
            for (int nf = 0; nf < 4; nf++) {
                int col = n0 + nf * 8 + tg * 2;
                if (r_lo < N)
                    *(float2*)(C + (size_t)r_lo * 256 + col) =
                        make_float2(acc[mf][nf][0], acc[mf][nf][1]);
                if (r_hi < N)
                    *(float2*)(C + (size_t)r_hi * 256 + col) =
                        make_float2(acc[mf][nf][2], acc[mf][nf][3]);
            }
        }
    }
}

// ---------------------------------------------------------------------------
// Per-pair: h = relu(C[src][0:128] + C[dst][128:256] + b1); logits = h@W2+b2;
// loss_i = logsumexp(softmax(logits)) - softmax(logits)[label]; atomic mean.
// One warp per pair (grid-strided), lane owns 4 features.
// ---------------------------------------------------------------------------
__global__ void pair_kernel(const int* __restrict__ pairs,
                            const int* __restrict__ labels,
                            const float* __restrict__ C,
                            const float* __restrict__ b1,
                            const float* __restrict__ W2,
                            const float* __restrict__ b2,
                            float* __restrict__ out, int B) {
    int lane = threadIdx.x & 31;
    int wib = threadIdx.x >> 5;
    int warpsPerBlock = blockDim.x >> 5;
    int gwarp = blockIdx.x * warpsPerBlock + wib;
    int nwarps = gridDim.x * warpsPerBlock;

    float4 bias = __ldg((const float4*)b1 + lane);
    float w20[4], w21[4];
#pragma unroll
    for (int q = 0; q < 4; q++) {
        w20[q] = __ldg(W2 + (lane * 4 + q) * 2 + 0);
        w21[q] = __ldg(W2 + (lane * 4 + q) * 2 + 1);
    }
    float b2_0 = __ldg(b2 + 0), b2_1 = __ldg(b2 + 1);

    const float4* C4 = (const float4*)C;
    float lsum = 0.f;

    for (int p = gwarp; p < B; p += nwarps) {
        int src = __ldg(pairs + 2 * p);
        int dst = __ldg(pairs + 2 * p + 1);
        float4 a  = __ldg(C4 + (size_t)src * 64 + lane);
        float4 bb = __ldg(C4 + (size_t)dst * 64 + 32 + lane);
        float h0 = fmaxf(a.x + bb.x + bias.x, 0.f);
        float h1 = fmaxf(a.y + bb.y + bias.y, 0.f);
        float h2 = fmaxf(a.z + bb.z + bias.z, 0.f);
        float h3 = fmaxf(a.w + bb.w + bias.w, 0.f);
        float l0 = h0 * w20[0] + h1 * w20[1] + h2 * w20[2] + h3 * w20[3];
        float l1 = h0 * w21[0] + h1 * w21[1] + h2 * w21[2] + h3 * w21[3];
#pragma unroll
        for (int off = 16; off > 0; off >>= 1) {
            l0 += __shfl_down_sync(0xFFFFFFFFu, l0, off);
            l1 += __shfl_down_sync(0xFFFFFFFFu, l1, off);
        }
        if (lane == 0) {
            l0 += b2_0; l1 += b2_1;
            // probs = softmax(logits)
            float m = fmaxf(l0, l1);
            float e0 = expf(l0 - m), e1 = expf(l1 - m);
            float inv = 1.f / (e0 + e1);
            float p0 = e0 * inv, p1 = e1 * inv;
            // logp = probs - logsumexp(probs)
            float mm = fmaxf(p0, p1);
            float lse = mm + logf(expf(p0 - mm) + expf(p1 - mm));
            int lab = __ldg(labels + p);
            float pl = lab ? p1 : p0;
            lsum += (lse - pl);
        }
    }

    __shared__ float ssum[32];
    if (lane == 0) ssum[wib] = lsum;
    __syncthreads();
    if (threadIdx.x == 0) {
        float s = 0.f;
        for (int w = 0; w < warpsPerBlock; w++) s += ssum[w];
        atomicAdd(out, s / (float)B);
    }
}

__global__ void zero_kernel(float* out, int n) {
    int i = blockIdx.x * blockDim.x + threadIdx.x;
    if (i < n) out[i] = 0.f;
}

// ---------------------------------------------------------------------------
extern "C" void kernel_launch(void* const* d_in, const int* in_sizes, int n_in,
                              void* d_out, int out_size) {
    const int*   pairs     = (const int*)d_in[0];
    const int*   labels    = (const int*)d_in[1];
    const int*   neighbors = (const int*)d_in[2];
    const float* embedding = (const float*)d_in[3];
    const float* W1        = (const float*)d_in[4];
    const float* b1        = (const float*)d_in[5];
    const float* W2        = (const float*)d_in[6];
    const float* b2        = (const float*)d_in[7];

    int B = in_sizes[0] / 2;
    int N = in_sizes[2] / KNBR;

    __half *E, *H1, *H2;
    float* C;
    cudaGetSymbolAddress((void**)&E,  g_E);
    cudaGetSymbolAddress((void**)&H1, g_H1);
    cudaGetSymbolAddress((void**)&H2, g_H2);
    cudaGetSymbolAddress((void**)&C,  g_C);

    float* out = (float*)d_out;
    zero_kernel<<<(out_size + 255) / 256, 256>>>(out, out_size);

    // Convert embedding to fp16
    int n4 = N * DIM / 4;
    f2h_kernel<<<(n4 + 255) / 256, 256>>>(embedding, E, n4);

    // 2 aggregation layers (fp16 gathers, fp32 accumulate)
    int aggBlocks = (N + 7) / 8;  // 8 warps/block, warp per node
    agg_kernel<<<aggBlocks, 256>>>(E,  neighbors, H1, N);
    agg_kernel<<<aggBlocks, 256>>>(H1, neighbors, H2, N);

    // Projection GEMM: C = H2 @ Wcat  (fp16 mma, 2 CTAs/SM)
    size_t smem = (size_t)(256 * HSW + 64 * HSW) * sizeof(unsigned);  // 87040 B
    cudaFuncSetAttribute(gemm_kernel, cudaFuncAttributeMaxDynamicSharedMemorySize, (int)smem);
    gemm_kernel<<<296, 256, smem>>>(H2, W1, C, N);

    // Pair loss
    pair_kernel<<<1184, 256>>>(pairs, labels, C, b1, W2, b2, out, B);
}